// round 1
// baseline (speedup 1.0000x reference)
#include <cuda_runtime.h>
#include <cuda_bf16.h>
#include <math.h>

// Problem constants
#define SEQ 256
#define BATCH 8
#define NNODES 2048
#define DMODEL 256
#define NHEAD 8
#define DK 32
#define DFF 1024
#define NLAYERS 2
#define VOCAB 259

// ---------------- scratch (static __device__, no allocation) ----------------
__device__ float g_x[NNODES * DMODEL];
__device__ float g_xn[NNODES * DMODEL];
__device__ float g_qkv[NNODES * 3 * DMODEL];
__device__ float g_z[NNODES * DMODEL];
__device__ float g_h[NNODES * DFF];
__device__ float g_logits[NNODES * VOCAB];

// ---------------- embed ----------------
__global__ void embed_kernel(const int* __restrict__ tokens,
                             const int* __restrict__ positions,
                             const float* __restrict__ coord_emb,
                             const float* __restrict__ pos_emb,
                             const float* __restrict__ value_emb,
                             float* __restrict__ x) {
    int row = blockIdx.x;
    int d = threadIdx.x;
    int p = positions[row];
    int t = tokens[row];
    float v = coord_emb[(p % 3) * DMODEL + d]
            + pos_emb[(p / 3) * DMODEL + d]
            + value_emb[t * DMODEL + d];
    x[row * DMODEL + d] = v;
}

// ---------------- layernorm (one block per row, 256 threads) ----------------
__global__ void ln_kernel(const float* __restrict__ x,
                          const float* __restrict__ scale,
                          const float* __restrict__ bias,
                          float* __restrict__ y) {
    int row = blockIdx.x;
    int d = threadIdx.x;
    float v = x[row * DMODEL + d];
    float s = v, s2 = v * v;
    #pragma unroll
    for (int o = 16; o > 0; o >>= 1) {
        s  += __shfl_down_sync(0xffffffffu, s, o);
        s2 += __shfl_down_sync(0xffffffffu, s2, o);
    }
    __shared__ float sh[8], sh2[8];
    int w = d >> 5, l = d & 31;
    if (l == 0) { sh[w] = s; sh2[w] = s2; }
    __syncthreads();
    __shared__ float mu_s, rstd_s;
    if (d == 0) {
        float ts = 0.f, ts2 = 0.f;
        #pragma unroll
        for (int i = 0; i < 8; i++) { ts += sh[i]; ts2 += sh2[i]; }
        float mu = ts * (1.0f / DMODEL);
        float var = ts2 * (1.0f / DMODEL) - mu * mu;
        mu_s = mu;
        rstd_s = rsqrtf(var + 1e-5f);
    }
    __syncthreads();
    y[row * DMODEL + d] = (v - mu_s) * rstd_s * scale[d] + bias[d];
}

// ---------------- tiled GEMM: C = [res +] act(A@B [+ bias]) ----------------
// A: MxK row-major, B: KxN row-major. 64x64 tile, BK=16, 256 threads, 4x4/thread.
// flags: bit0 = relu (applied to A@B+bias before residual add)
__global__ void gemm_kernel(const float* __restrict__ A,
                            const float* __restrict__ B,
                            const float* __restrict__ bias,
                            const float* __restrict__ res,
                            float* __restrict__ C,
                            int M, int N, int K, int flags) {
    __shared__ float As[16][64];
    __shared__ float Bs[16][64 + 4];
    int tid = threadIdx.x;
    int tx = tid & 15, ty = tid >> 4;
    int bm = blockIdx.y * 64, bn = blockIdx.x * 64;

    float c[4][4];
    #pragma unroll
    for (int i = 0; i < 4; i++)
        #pragma unroll
        for (int j = 0; j < 4; j++) c[i][j] = 0.f;

    int arow = tid >> 2, acol0 = (tid & 3) * 4;   // A: 64 rows x 16 cols
    int brow = tid >> 4, bcol0 = (tid & 15) * 4;  // B: 16 rows x 64 cols
    bool n_vec = ((N & 3) == 0);

    for (int k0 = 0; k0 < K; k0 += 16) {
        // load A tile (M=2048 multiple of 64, K multiple of 16 -> no bounds)
        {
            const float* Ap = A + (size_t)(bm + arow) * K + k0 + acol0;
            float4 v = *(const float4*)Ap;
            As[acol0 + 0][arow] = v.x;
            As[acol0 + 1][arow] = v.y;
            As[acol0 + 2][arow] = v.z;
            As[acol0 + 3][arow] = v.w;
        }
        // load B tile
        {
            int gk = k0 + brow;
            int gn = bn + bcol0;
            if (n_vec) {
                float4 v = *(const float4*)(B + (size_t)gk * N + gn);
                Bs[brow][bcol0 + 0] = v.x;
                Bs[brow][bcol0 + 1] = v.y;
                Bs[brow][bcol0 + 2] = v.z;
                Bs[brow][bcol0 + 3] = v.w;
            } else {
                #pragma unroll
                for (int i = 0; i < 4; i++) {
                    int n = gn + i;
                    Bs[brow][bcol0 + i] = (n < N) ? B[(size_t)gk * N + n] : 0.f;
                }
            }
        }
        __syncthreads();
        #pragma unroll
        for (int kk = 0; kk < 16; kk++) {
            float a[4], b[4];
            #pragma unroll
            for (int i = 0; i < 4; i++) a[i] = As[kk][ty * 4 + i];
            #pragma unroll
            for (int j = 0; j < 4; j++) b[j] = Bs[kk][tx * 4 + j];
            #pragma unroll
            for (int i = 0; i < 4; i++)
                #pragma unroll
                for (int j = 0; j < 4; j++)
                    c[i][j] = fmaf(a[i], b[j], c[i][j]);
        }
        __syncthreads();
    }

    bool do_relu = (flags & 1);
    #pragma unroll
    for (int i = 0; i < 4; i++) {
        int m = bm + ty * 4 + i;
        #pragma unroll
        for (int j = 0; j < 4; j++) {
            int n = bn + tx * 4 + j;
            if (n < N) {
                float t = c[i][j];
                if (bias) t += bias[n];
                if (do_relu) t = fmaxf(t, 0.f);
                if (res) t += res[(size_t)m * N + n];
                C[(size_t)m * N + n] = t;
            }
        }
    }
}

// ---------------- causal attention ----------------
// grid = BATCH*NHEAD blocks, 256 threads; thread q = one query row.
// qkv layout per node: [3][H][DK] -> Q at col h*32, K at 256+h*32, V at 512+h*32.
__global__ void attn_kernel(const float* __restrict__ qkv, float* __restrict__ z) {
    int b = blockIdx.x >> 3;
    int h = blockIdx.x & 7;
    int q = threadIdx.x;
    int node0 = b * SEQ;

    extern __shared__ float smem[];
    float* Ks = smem;             // 256*32
    float* Vs = smem + SEQ * DK;  // 256*32

    // stage K,V rows (thread q loads row q)
    {
        const float* kp = qkv + (size_t)(node0 + q) * (3 * DMODEL) + DMODEL + h * DK;
        const float* vp = kp + DMODEL;
        #pragma unroll
        for (int i = 0; i < 8; i++) {
            ((float4*)(Ks + q * DK))[i] = ((const float4*)kp)[i];
            ((float4*)(Vs + q * DK))[i] = ((const float4*)vp)[i];
        }
    }
    float4 qv[8];
    {
        const float* qp = qkv + (size_t)(node0 + q) * (3 * DMODEL) + h * DK;
        #pragma unroll
        for (int i = 0; i < 8; i++) qv[i] = ((const float4*)qp)[i];
    }
    __syncthreads();

    const float scale = 0.1767766952966369f;  // 1/sqrt(32)
    float m = -1e30f, l = 0.f;
    float4 acc[8];
    #pragma unroll
    for (int i = 0; i < 8; i++) acc[i] = make_float4(0.f, 0.f, 0.f, 0.f);

    int jmax = q | 31;  // warp-uniform trip count -> smem broadcast preserved
    for (int j = 0; j <= jmax; j++) {
        const float4* kr = (const float4*)(Ks + j * DK);
        float s = 0.f;
        #pragma unroll
        for (int i = 0; i < 8; i++) {
            float4 kvv = kr[i];
            s = fmaf(qv[i].x, kvv.x, s);
            s = fmaf(qv[i].y, kvv.y, s);
            s = fmaf(qv[i].z, kvv.z, s);
            s = fmaf(qv[i].w, kvv.w, s);
        }
        s *= scale;
        if (j > q) s = -1e30f;  // causal mask -> p = 0
        float mn = fmaxf(m, s);
        float corr = expf(m - mn);
        float p = expf(s - mn);
        l = l * corr + p;
        const float4* vr = (const float4*)(Vs + j * DK);
        #pragma unroll
        for (int i = 0; i < 8; i++) {
            float4 vv = vr[i];
            acc[i].x = acc[i].x * corr + p * vv.x;
            acc[i].y = acc[i].y * corr + p * vv.y;
            acc[i].z = acc[i].z * corr + p * vv.z;
            acc[i].w = acc[i].w * corr + p * vv.w;
        }
        m = mn;
    }
    float inv = 1.f / l;
    float* zp = z + (size_t)(node0 + q) * DMODEL + h * DK;
    #pragma unroll
    for (int i = 0; i < 8; i++) {
        float4 o = acc[i];
        o.x *= inv; o.y *= inv; o.z *= inv; o.w *= inv;
        ((float4*)zp)[i] = o;
    }
}

// ---------------- log-softmax over VOCAB=259 ----------------
__global__ void lsm_kernel(const float* __restrict__ logits, float* __restrict__ out) {
    int row = blockIdx.x;
    int tid = threadIdx.x;  // 256
    const float* lp = logits + (size_t)row * VOCAB;
    float v0 = lp[tid];
    float v1 = (tid < VOCAB - 256) ? lp[256 + tid] : -1e30f;
    float mx = fmaxf(v0, v1);
    #pragma unroll
    for (int o = 16; o > 0; o >>= 1)
        mx = fmaxf(mx, __shfl_down_sync(0xffffffffu, mx, o));
    __shared__ float shm[8];
    int w = tid >> 5, l = tid & 31;
    if (l == 0) shm[w] = mx;
    __syncthreads();
    __shared__ float M_s, lse_s;
    if (tid == 0) {
        float m = shm[0];
        #pragma unroll
        for (int i = 1; i < 8; i++) m = fmaxf(m, shm[i]);
        M_s = m;
    }
    __syncthreads();
    float M = M_s;
    float e = expf(v0 - M) + ((tid < VOCAB - 256) ? expf(v1 - M) : 0.f);
    #pragma unroll
    for (int o = 16; o > 0; o >>= 1)
        e += __shfl_down_sync(0xffffffffu, e, o);
    if (l == 0) shm[w] = e;
    __syncthreads();
    if (tid == 0) {
        float s = 0.f;
        #pragma unroll
        for (int i = 0; i < 8; i++) s += shm[i];
        lse_s = logf(s) + M;
    }
    __syncthreads();
    float lse = lse_s;
    float* op = out + (size_t)row * VOCAB;
    op[tid] = v0 - lse;
    if (tid < VOCAB - 256) op[256 + tid] = v1 - lse;
}

// ---------------- launch ----------------
extern "C" void kernel_launch(void* const* d_in, const int* in_sizes, int n_in,
                              void* d_out, int out_size) {
    const int*   tokens    = (const int*)d_in[0];
    const int*   positions = (const int*)d_in[1];
    // d_in[2], d_in[3]: edge_src/edge_dst — structure is tril_indices; handled analytically
    const float* coord_emb = (const float*)d_in[4];
    const float* pos_emb   = (const float*)d_in[5];
    const float* value_emb = (const float*)d_in[6];
    const float* ln1_scale = (const float*)d_in[7];
    const float* ln1_bias  = (const float*)d_in[8];
    const float* Wqkv      = (const float*)d_in[9];
    const float* Wo        = (const float*)d_in[10];
    const float* ln2_scale = (const float*)d_in[11];
    const float* ln2_bias  = (const float*)d_in[12];
    const float* W1        = (const float*)d_in[13];
    const float* b1        = (const float*)d_in[14];
    const float* W2        = (const float*)d_in[15];
    const float* b2        = (const float*)d_in[16];
    const float* lnf_scale = (const float*)d_in[17];
    const float* lnf_bias  = (const float*)d_in[18];
    const float* Wg        = (const float*)d_in[19];
    const float* bg        = (const float*)d_in[20];
    float* out = (float*)d_out;

    float *x, *xn, *qkv, *z, *h, *logits;
    cudaGetSymbolAddress((void**)&x, g_x);
    cudaGetSymbolAddress((void**)&xn, g_xn);
    cudaGetSymbolAddress((void**)&qkv, g_qkv);
    cudaGetSymbolAddress((void**)&z, g_z);
    cudaGetSymbolAddress((void**)&h, g_h);
    cudaGetSymbolAddress((void**)&logits, g_logits);

    cudaFuncSetAttribute(attn_kernel, cudaFuncAttributeMaxDynamicSharedMemorySize,
                         2 * SEQ * DK * sizeof(float));

    embed_kernel<<<NNODES, DMODEL>>>(tokens, positions, coord_emb, pos_emb, value_emb, x);

    for (int i = 0; i < NLAYERS; i++) {
        const float* wqkv_i = Wqkv + (size_t)i * DMODEL * 3 * DMODEL;
        const float* wo_i   = Wo   + (size_t)i * DMODEL * DMODEL;
        const float* w1_i   = W1   + (size_t)i * DMODEL * DFF;
        const float* w2_i   = W2   + (size_t)i * DFF * DMODEL;

        // attention block
        ln_kernel<<<NNODES, DMODEL>>>(x, ln1_scale + i * DMODEL, ln1_bias + i * DMODEL, xn);
        {
            dim3 grid((3 * DMODEL + 63) / 64, NNODES / 64);
            gemm_kernel<<<grid, 256>>>(xn, wqkv_i, nullptr, nullptr, qkv,
                                       NNODES, 3 * DMODEL, DMODEL, 0);
        }
        attn_kernel<<<BATCH * NHEAD, SEQ, 2 * SEQ * DK * sizeof(float)>>>(qkv, z);
        {
            dim3 grid((DMODEL + 63) / 64, NNODES / 64);
            gemm_kernel<<<grid, 256>>>(z, wo_i, nullptr, x, x,
                                       NNODES, DMODEL, DMODEL, 0);
        }
        // FFN block
        ln_kernel<<<NNODES, DMODEL>>>(x, ln2_scale + i * DMODEL, ln2_bias + i * DMODEL, xn);
        {
            dim3 grid((DFF + 63) / 64, NNODES / 64);
            gemm_kernel<<<grid, 256>>>(xn, w1_i, b1 + i * DFF, nullptr, h,
                                       NNODES, DFF, DMODEL, 1 /*relu*/);
        }
        {
            dim3 grid((DMODEL + 63) / 64, NNODES / 64);
            gemm_kernel<<<grid, 256>>>(h, w2_i, b2 + i * DMODEL, x, x,
                                       NNODES, DMODEL, DFF, 0);
        }
    }

    ln_kernel<<<NNODES, DMODEL>>>(x, lnf_scale, lnf_bias, xn);
    {
        dim3 grid((VOCAB + 63) / 64, NNODES / 64);
        gemm_kernel<<<grid, 256>>>(xn, Wg, bg, nullptr, logits,
                                   NNODES, VOCAB, DMODEL, 0);
    }
    lsm_kernel<<<NNODES, 256>>>(logits, out);
}

// round 3
// speedup vs baseline: 2.4374x; 2.4374x over previous
#include <cuda_runtime.h>
#include <cuda_bf16.h>
#include <math.h>
#include <stdint.h>

// Problem constants
#define SEQ 256
#define BATCH 8
#define NNODES 2048
#define DMODEL 256
#define NHEAD 8
#define DK 32
#define DFF 1024
#define NLAYERS 2
#define VOCAB 259
#define NSPLIT 4
#define SPLITK 64

// ---------------- scratch (static __device__, no allocation) ----------------
__device__ float g_x[NNODES * DMODEL];
__device__ float g_xn[NNODES * DMODEL];
__device__ float g_qkv[NNODES * 3 * DMODEL];
__device__ float g_z[NNODES * DMODEL];
__device__ float g_h[NNODES * DFF];
__device__ float g_logits[NNODES * VOCAB];
__device__ float g_pm[NSPLIT * NNODES * NHEAD];
__device__ float g_pl[NSPLIT * NNODES * NHEAD];
__device__ float g_pacc[NSPLIT * NNODES * NHEAD * DK];

// ---------------- embed ----------------
__global__ void embed_kernel(const int* __restrict__ tokens,
                             const int* __restrict__ positions,
                             const float* __restrict__ coord_emb,
                             const float* __restrict__ pos_emb,
                             const float* __restrict__ value_emb,
                             float* __restrict__ x) {
    int row = blockIdx.x;
    int d = threadIdx.x;
    int p = positions[row];
    int t = tokens[row];
    float v = coord_emb[(p % 3) * DMODEL + d]
            + pos_emb[(p / 3) * DMODEL + d]
            + value_emb[t * DMODEL + d];
    x[row * DMODEL + d] = v;
}

// ---------------- layernorm (one block per row, 256 threads) ----------------
__global__ void ln_kernel(const float* __restrict__ x,
                          const float* __restrict__ scale,
                          const float* __restrict__ bias,
                          float* __restrict__ y) {
    int row = blockIdx.x;
    int d = threadIdx.x;
    float v = x[row * DMODEL + d];
    float s = v, s2 = v * v;
    #pragma unroll
    for (int o = 16; o > 0; o >>= 1) {
        s  += __shfl_down_sync(0xffffffffu, s, o);
        s2 += __shfl_down_sync(0xffffffffu, s2, o);
    }
    __shared__ float sh[8], sh2[8];
    int w = d >> 5, l = d & 31;
    if (l == 0) { sh[w] = s; sh2[w] = s2; }
    __syncthreads();
    __shared__ float mu_s, rstd_s;
    if (d == 0) {
        float ts = 0.f, ts2 = 0.f;
        #pragma unroll
        for (int i = 0; i < 8; i++) { ts += sh[i]; ts2 += sh2[i]; }
        float mu = ts * (1.0f / DMODEL);
        float var = ts2 * (1.0f / DMODEL) - mu * mu;
        mu_s = mu;
        rstd_s = rsqrtf(var + 1e-5f);
    }
    __syncthreads();
    y[row * DMODEL + d] = (v - mu_s) * rstd_s * scale[d] + bias[d];
}

// ---------------- tf32 tensor-core GEMM ----------------
// C = [res +] act(A@B [+ bias]); A: MxK rm, B: KxN rm.
// Block tile 64x64, BK=32, 256 threads = 8 warps (4m x 2n), warp tile 16x32.
#define BM 64
#define BN 64
#define BKT 32
#define A_LD 36
#define B_LD 72

__device__ __forceinline__ uint32_t f2tf(float f) {
    uint32_t u;
    asm("cvt.rna.tf32.f32 %0, %1;" : "=r"(u) : "f"(f));
    return u;
}

__device__ __forceinline__ void mma8(float* c, const uint32_t* a, const uint32_t* b) {
    asm volatile(
        "mma.sync.aligned.m16n8k8.row.col.f32.tf32.tf32.f32 "
        "{%0,%1,%2,%3},{%4,%5,%6,%7},{%8,%9},{%0,%1,%2,%3};"
        : "+f"(c[0]), "+f"(c[1]), "+f"(c[2]), "+f"(c[3])
        : "r"(a[0]), "r"(a[1]), "r"(a[2]), "r"(a[3]), "r"(b[0]), "r"(b[1]));
}

__global__ __launch_bounds__(256) void gemm_tc(const float* __restrict__ A,
                                               const float* __restrict__ B,
                                               const float* __restrict__ bias,
                                               const float* __restrict__ res,
                                               float* __restrict__ C,
                                               int M, int N, int K, int flags) {
    __shared__ uint32_t As[2][BM * A_LD];
    __shared__ uint32_t Bs[2][BKT * B_LD];
    int tid = threadIdx.x;
    int lane = tid & 31, wid = tid >> 5;
    int wm = wid & 3, wn = wid >> 2;       // 4 x 2 warp grid
    int grp = lane >> 2, qk = lane & 3;
    int bm = blockIdx.y * BM, bn = blockIdx.x * BN;
    // float4 on B requires both in-bounds AND 16B-aligned rows (N % 4 == 0).
    bool bvec = ((N & 3) == 0) && (bn + BN <= N);

    float c[4][4];
    #pragma unroll
    for (int i = 0; i < 4; i++)
        #pragma unroll
        for (int j = 0; j < 4; j++) c[i][j] = 0.f;

    float4 ra[2], rb[2];

    // ---- prologue: load k0=0 ----
    {
        #pragma unroll
        for (int i = 0; i < 2; i++) {
            int idx = tid + 256 * i;
            int m = idx >> 3, kq = idx & 7;
            ra[i] = *(const float4*)(A + (size_t)(bm + m) * K + kq * 4);
        }
        #pragma unroll
        for (int i = 0; i < 2; i++) {
            int idx = tid + 256 * i;
            int k = idx >> 4, nq = idx & 15;
            if (bvec) {
                rb[i] = *(const float4*)(B + (size_t)k * N + bn + nq * 4);
            } else {
                int n = bn + nq * 4;
                rb[i].x = (n + 0 < N) ? B[(size_t)k * N + n + 0] : 0.f;
                rb[i].y = (n + 1 < N) ? B[(size_t)k * N + n + 1] : 0.f;
                rb[i].z = (n + 2 < N) ? B[(size_t)k * N + n + 2] : 0.f;
                rb[i].w = (n + 3 < N) ? B[(size_t)k * N + n + 3] : 0.f;
            }
        }
        #pragma unroll
        for (int i = 0; i < 2; i++) {
            int idx = tid + 256 * i;
            int m = idx >> 3, kq = idx & 7;
            uint32_t* p = &As[0][m * A_LD + kq * 4];
            p[0] = f2tf(ra[i].x); p[1] = f2tf(ra[i].y);
            p[2] = f2tf(ra[i].z); p[3] = f2tf(ra[i].w);
        }
        #pragma unroll
        for (int i = 0; i < 2; i++) {
            int idx = tid + 256 * i;
            int k = idx >> 4, nq = idx & 15;
            uint32_t* p = &Bs[0][k * B_LD + nq * 4];
            p[0] = f2tf(rb[i].x); p[1] = f2tf(rb[i].y);
            p[2] = f2tf(rb[i].z); p[3] = f2tf(rb[i].w);
        }
    }
    __syncthreads();

    int nk = K / BKT;
    for (int it = 0; it < nk; it++) {
        int buf = it & 1;
        bool has_next = (it + 1 < nk);
        if (has_next) {
            int k0 = (it + 1) * BKT;
            #pragma unroll
            for (int i = 0; i < 2; i++) {
                int idx = tid + 256 * i;
                int m = idx >> 3, kq = idx & 7;
                ra[i] = *(const float4*)(A + (size_t)(bm + m) * K + k0 + kq * 4);
            }
            #pragma unroll
            for (int i = 0; i < 2; i++) {
                int idx = tid + 256 * i;
                int k = idx >> 4, nq = idx & 15;
                if (bvec) {
                    rb[i] = *(const float4*)(B + (size_t)(k0 + k) * N + bn + nq * 4);
                } else {
                    int n = bn + nq * 4;
                    rb[i].x = (n + 0 < N) ? B[(size_t)(k0 + k) * N + n + 0] : 0.f;
                    rb[i].y = (n + 1 < N) ? B[(size_t)(k0 + k) * N + n + 1] : 0.f;
                    rb[i].z = (n + 2 < N) ? B[(size_t)(k0 + k) * N + n + 2] : 0.f;
                    rb[i].w = (n + 3 < N) ? B[(size_t)(k0 + k) * N + n + 3] : 0.f;
                }
            }
        }
        // compute on buf
        #pragma unroll
        for (int kk = 0; kk < BKT; kk += 8) {
            uint32_t a[4];
            int m0 = wm * 16 + grp;
            a[0] = As[buf][(m0) * A_LD + kk + qk];
            a[1] = As[buf][(m0 + 8) * A_LD + kk + qk];
            a[2] = As[buf][(m0) * A_LD + kk + qk + 4];
            a[3] = As[buf][(m0 + 8) * A_LD + kk + qk + 4];
            #pragma unroll
            for (int sj = 0; sj < 4; sj++) {
                uint32_t b[2];
                int n0 = wn * 32 + sj * 8 + grp;
                b[0] = Bs[buf][(kk + qk) * B_LD + n0];
                b[1] = Bs[buf][(kk + qk + 4) * B_LD + n0];
                mma8(c[sj], a, b);
            }
        }
        if (has_next) {
            int nb = (it + 1) & 1;
            #pragma unroll
            for (int i = 0; i < 2; i++) {
                int idx = tid + 256 * i;
                int m = idx >> 3, kq = idx & 7;
                uint32_t* p = &As[nb][m * A_LD + kq * 4];
                p[0] = f2tf(ra[i].x); p[1] = f2tf(ra[i].y);
                p[2] = f2tf(ra[i].z); p[3] = f2tf(ra[i].w);
            }
            #pragma unroll
            for (int i = 0; i < 2; i++) {
                int idx = tid + 256 * i;
                int k = idx >> 4, nq = idx & 15;
                uint32_t* p = &Bs[nb][k * B_LD + nq * 4];
                p[0] = f2tf(rb[i].x); p[1] = f2tf(rb[i].y);
                p[2] = f2tf(rb[i].z); p[3] = f2tf(rb[i].w);
            }
            __syncthreads();
        }
    }

    // ---- epilogue ----
    bool do_relu = (flags & 1);
    int r0 = bm + wm * 16 + grp;
    int r1 = r0 + 8;
    #pragma unroll
    for (int sj = 0; sj < 4; sj++) {
        int n = bn + wn * 32 + sj * 8 + qk * 2;
        #pragma unroll
        for (int jj = 0; jj < 2; jj++) {
            int nn = n + jj;
            if (nn < N) {
                float bv = bias ? bias[nn] : 0.f;
                float t0 = c[sj][0 + jj] + bv;
                float t1 = c[sj][2 + jj] + bv;
                if (do_relu) { t0 = fmaxf(t0, 0.f); t1 = fmaxf(t1, 0.f); }
                if (res) {
                    t0 += res[(size_t)r0 * N + nn];
                    t1 += res[(size_t)r1 * N + nn];
                }
                C[(size_t)r0 * N + nn] = t0;
                C[(size_t)r1 * N + nn] = t1;
            }
        }
    }
}

// ---------------- causal attention, split-K partials ----------------
// grid = (BATCH*NHEAD, NSPLIT), 256 threads; thread q = one query row.
__global__ __launch_bounds__(256) void attn_part(const float* __restrict__ qkv) {
    int bh = blockIdx.x;
    int s = blockIdx.y;
    int b = bh >> 3;
    int h = bh & 7;
    int q = threadIdx.x;
    int node0 = b * SEQ;
    int kbase = s * SPLITK;

    __shared__ float Ks[SPLITK * DK];
    __shared__ float Vs[SPLITK * DK];

    // stage K/V slice: 64 rows x 32 floats = 512 float4, 2 per thread
    #pragma unroll
    for (int i = 0; i < 2; i++) {
        int idx = threadIdx.x + 256 * i;
        int row = idx >> 3, fq = idx & 7;
        const float* kp = qkv + (size_t)(node0 + kbase + row) * (3 * DMODEL) + DMODEL + h * DK;
        const float* vp = kp + DMODEL;
        ((float4*)Ks)[row * 8 + fq] = ((const float4*)kp)[fq];
        ((float4*)Vs)[row * 8 + fq] = ((const float4*)vp)[fq];
    }

    float4 qv[8];
    {
        const float* qp = qkv + (size_t)(node0 + q) * (3 * DMODEL) + h * DK;
        #pragma unroll
        for (int i = 0; i < 8; i++) qv[i] = ((const float4*)qp)[i];
    }
    __syncthreads();

    int node = node0 + q;
    int pidx = (s * NNODES + node) * NHEAD + h;

    float m = -1e30f, l = 0.f;
    float4 acc[8];
    #pragma unroll
    for (int i = 0; i < 8; i++) acc[i] = make_float4(0.f, 0.f, 0.f, 0.f);

    if (q >= kbase) {
        const float scale = 0.1767766952966369f;  // 1/sqrt(32)
        int lim = q - kbase;                       // mask: local j <= lim
        if (lim > SPLITK - 1) lim = SPLITK - 1;
        int jmaxw = (q - kbase) | 31;              // warp-uniform
        if (jmaxw > SPLITK - 1) jmaxw = SPLITK - 1;
        for (int j = 0; j <= jmaxw; j++) {
            const float4* kr = (const float4*)(Ks + j * DK);
            float sc = 0.f;
            #pragma unroll
            for (int i = 0; i < 8; i++) {
                float4 kvv = kr[i];
                sc = fmaf(qv[i].x, kvv.x, sc);
                sc = fmaf(qv[i].y, kvv.y, sc);
                sc = fmaf(qv[i].z, kvv.z, sc);
                sc = fmaf(qv[i].w, kvv.w, sc);
            }
            sc *= scale;
            if (j > lim) sc = -1e30f;
            float mn = fmaxf(m, sc);
            float corr = expf(m - mn);
            float p = expf(sc - mn);
            l = l * corr + p;
            const float4* vr = (const float4*)(Vs + j * DK);
            #pragma unroll
            for (int i = 0; i < 8; i++) {
                float4 vv = vr[i];
                acc[i].x = acc[i].x * corr + p * vv.x;
                acc[i].y = acc[i].y * corr + p * vv.y;
                acc[i].z = acc[i].z * corr + p * vv.z;
                acc[i].w = acc[i].w * corr + p * vv.w;
            }
            m = mn;
        }
        float* ap = g_pacc + (size_t)pidx * DK;
        #pragma unroll
        for (int i = 0; i < 8; i++) ((float4*)ap)[i] = acc[i];
    }
    g_pm[pidx] = m;
    g_pl[pidx] = l;
}

// combine: grid NNODES, 256 threads = 8 heads x 32 dims
__global__ void attn_combine(float* __restrict__ z) {
    int node = blockIdx.x;
    int h = threadIdx.x >> 5;
    int d = threadIdx.x & 31;

    float ms[NSPLIT], ls[NSPLIT];
    float M = -1e30f;
    #pragma unroll
    for (int s = 0; s < NSPLIT; s++) {
        int pidx = (s * NNODES + node) * NHEAD + h;
        ms[s] = g_pm[pidx];
        ls[s] = g_pl[pidx];
        M = fmaxf(M, ms[s]);
    }
    float wsum = 0.f, zz = 0.f;
    #pragma unroll
    for (int s = 0; s < NSPLIT; s++) {
        float w = expf(ms[s] - M);
        wsum += ls[s] * w;
        int pidx = (s * NNODES + node) * NHEAD + h;
        zz += w * g_pacc[(size_t)pidx * DK + d];
    }
    z[(size_t)node * DMODEL + h * DK + d] = zz / wsum;
}

// ---------------- log-softmax over VOCAB=259 ----------------
__global__ void lsm_kernel(const float* __restrict__ logits, float* __restrict__ out) {
    int row = blockIdx.x;
    int tid = threadIdx.x;  // 256
    const float* lp = logits + (size_t)row * VOCAB;
    float v0 = lp[tid];
    float v1 = (tid < VOCAB - 256) ? lp[256 + tid] : -1e30f;
    float mx = fmaxf(v0, v1);
    #pragma unroll
    for (int o = 16; o > 0; o >>= 1)
        mx = fmaxf(mx, __shfl_down_sync(0xffffffffu, mx, o));
    __shared__ float shm[8];
    int w = tid >> 5, l = tid & 31;
    if (l == 0) shm[w] = mx;
    __syncthreads();
    __shared__ float M_s, lse_s;
    if (tid == 0) {
        float m = shm[0];
        #pragma unroll
        for (int i = 1; i < 8; i++) m = fmaxf(m, shm[i]);
        M_s = m;
    }
    __syncthreads();
    float M = M_s;
    float e = expf(v0 - M) + ((tid < VOCAB - 256) ? expf(v1 - M) : 0.f);
    #pragma unroll
    for (int o = 16; o > 0; o >>= 1)
        e += __shfl_down_sync(0xffffffffu, e, o);
    if (l == 0) shm[w] = e;
    __syncthreads();
    if (tid == 0) {
        float s = 0.f;
        #pragma unroll
        for (int i = 0; i < 8; i++) s += shm[i];
        lse_s = logf(s) + M;
    }
    __syncthreads();
    float lse = lse_s;
    float* op = out + (size_t)row * VOCAB;
    op[tid] = v0 - lse;
    if (tid < VOCAB - 256) op[256 + tid] = v1 - lse;
}

// ---------------- launch ----------------
extern "C" void kernel_launch(void* const* d_in, const int* in_sizes, int n_in,
                              void* d_out, int out_size) {
    const int*   tokens    = (const int*)d_in[0];
    const int*   positions = (const int*)d_in[1];
    // d_in[2], d_in[3]: edge_src/edge_dst — exact tril structure, handled analytically
    const float* coord_emb = (const float*)d_in[4];
    const float* pos_emb   = (const float*)d_in[5];
    const float* value_emb = (const float*)d_in[6];
    const float* ln1_scale = (const float*)d_in[7];
    const float* ln1_bias  = (const float*)d_in[8];
    const float* Wqkv      = (const float*)d_in[9];
    const float* Wo        = (const float*)d_in[10];
    const float* ln2_scale = (const float*)d_in[11];
    const float* ln2_bias  = (const float*)d_in[12];
    const float* W1        = (const float*)d_in[13];
    const float* b1        = (const float*)d_in[14];
    const float* W2        = (const float*)d_in[15];
    const float* b2        = (const float*)d_in[16];
    const float* lnf_scale = (const float*)d_in[17];
    const float* lnf_bias  = (const float*)d_in[18];
    const float* Wg        = (const float*)d_in[19];
    const float* bg        = (const float*)d_in[20];
    float* out = (float*)d_out;

    float *x, *xn, *qkv, *z, *h, *logits;
    cudaGetSymbolAddress((void**)&x, g_x);
    cudaGetSymbolAddress((void**)&xn, g_xn);
    cudaGetSymbolAddress((void**)&qkv, g_qkv);
    cudaGetSymbolAddress((void**)&z, g_z);
    cudaGetSymbolAddress((void**)&h, g_h);
    cudaGetSymbolAddress((void**)&logits, g_logits);

    embed_kernel<<<NNODES, DMODEL>>>(tokens, positions, coord_emb, pos_emb, value_emb, x);

    for (int i = 0; i < NLAYERS; i++) {
        const float* wqkv_i = Wqkv + (size_t)i * DMODEL * 3 * DMODEL;
        const float* wo_i   = Wo   + (size_t)i * DMODEL * DMODEL;
        const float* w1_i   = W1   + (size_t)i * DMODEL * DFF;
        const float* w2_i   = W2   + (size_t)i * DFF * DMODEL;

        // attention block
        ln_kernel<<<NNODES, DMODEL>>>(x, ln1_scale + i * DMODEL, ln1_bias + i * DMODEL, xn);
        {
            dim3 grid((3 * DMODEL) / BN, NNODES / BM);
            gemm_tc<<<grid, 256>>>(xn, wqkv_i, nullptr, nullptr, qkv,
                                   NNODES, 3 * DMODEL, DMODEL, 0);
        }
        attn_part<<<dim3(BATCH * NHEAD, NSPLIT), SEQ>>>(qkv);
        attn_combine<<<NNODES, 256>>>(z);
        {
            dim3 grid(DMODEL / BN, NNODES / BM);
            gemm_tc<<<grid, 256>>>(z, wo_i, nullptr, x, x,
                                   NNODES, DMODEL, DMODEL, 0);
        }
        // FFN block
        ln_kernel<<<NNODES, DMODEL>>>(x, ln2_scale + i * DMODEL, ln2_bias + i * DMODEL, xn);
        {
            dim3 grid(DFF / BN, NNODES / BM);
            gemm_tc<<<grid, 256>>>(xn, w1_i, b1 + i * DFF, nullptr, h,
                                   NNODES, DFF, DMODEL, 1 /*relu*/);
        }
        {
            dim3 grid(DMODEL / BN, NNODES / BM);
            gemm_tc<<<grid, 256>>>(h, w2_i, b2 + i * DMODEL, x, x,
                                   NNODES, DMODEL, DFF, 0);
        }
    }

    ln_kernel<<<NNODES, DMODEL>>>(x, lnf_scale, lnf_bias, xn);
    {
        dim3 grid((VOCAB + BN - 1) / BN, NNODES / BM);
        gemm_tc<<<grid, 256>>>(xn, Wg, bg, nullptr, logits,
                               NNODES, VOCAB, DMODEL, 0);
    }
    lsm_kernel<<<NNODES, 256>>>(logits, out);
}

// round 4
// speedup vs baseline: 2.4862x; 1.0200x over previous
#include <cuda_runtime.h>
#include <cuda_bf16.h>
#include <math.h>
#include <stdint.h>

// Problem constants
#define SEQ 256
#define BATCH 8
#define NNODES 2048
#define DMODEL 256
#define NHEAD 8
#define DK 32
#define DFF 1024
#define NLAYERS 2
#define VOCAB 259
#define NSPLIT 4
#define SPLITK 64

// ---------------- scratch (static __device__, no allocation) ----------------
__device__ float g_x[NNODES * DMODEL];
__device__ float g_xn[NNODES * DMODEL];
__device__ float g_qkv[NNODES * 3 * DMODEL];
__device__ float g_z[NNODES * DMODEL];
__device__ float g_h[NNODES * DFF];
__device__ float g_logits[NNODES * VOCAB];
__device__ float g_pm[NSPLIT * NNODES * NHEAD];
__device__ float g_pl[NSPLIT * NNODES * NHEAD];
__device__ float g_pacc[NSPLIT * NNODES * NHEAD * DK];

// ---------------- embed ----------------
__global__ void embed_kernel(const int* __restrict__ tokens,
                             const int* __restrict__ positions,
                             const float* __restrict__ coord_emb,
                             const float* __restrict__ pos_emb,
                             const float* __restrict__ value_emb,
                             float* __restrict__ x) {
    int row = blockIdx.x;
    int d = threadIdx.x;
    int p = positions[row];
    int t = tokens[row];
    float v = coord_emb[(p % 3) * DMODEL + d]
            + pos_emb[(p / 3) * DMODEL + d]
            + value_emb[t * DMODEL + d];
    x[row * DMODEL + d] = v;
}

// ---------------- layernorm: warp per row, 8 rows per block ----------------
__global__ __launch_bounds__(256) void ln_kernel(const float* __restrict__ x,
                                                 const float* __restrict__ scale,
                                                 const float* __restrict__ bias,
                                                 float* __restrict__ y) {
    int warp = threadIdx.x >> 5, lane = threadIdx.x & 31;
    int row = blockIdx.x * 8 + warp;
    const float4* xp = (const float4*)(x + (size_t)row * DMODEL + lane * 8);
    float4 a = xp[0], b = xp[1];
    float s  = a.x + a.y + a.z + a.w + b.x + b.y + b.z + b.w;
    float s2 = a.x*a.x + a.y*a.y + a.z*a.z + a.w*a.w
             + b.x*b.x + b.y*b.y + b.z*b.z + b.w*b.w;
    #pragma unroll
    for (int o = 16; o > 0; o >>= 1) {
        s  += __shfl_xor_sync(0xffffffffu, s, o);
        s2 += __shfl_xor_sync(0xffffffffu, s2, o);
    }
    float mu = s * (1.0f / DMODEL);
    float var = s2 * (1.0f / DMODEL) - mu * mu;
    float rstd = rsqrtf(var + 1e-5f);
    const float4* sp = (const float4*)(scale + lane * 8);
    const float4* bp = (const float4*)(bias + lane * 8);
    float4 s0 = sp[0], s1 = sp[1], b0 = bp[0], b1 = bp[1];
    float4 o0, o1;
    o0.x = (a.x - mu) * rstd * s0.x + b0.x;
    o0.y = (a.y - mu) * rstd * s0.y + b0.y;
    o0.z = (a.z - mu) * rstd * s0.z + b0.z;
    o0.w = (a.w - mu) * rstd * s0.w + b0.w;
    o1.x = (b.x - mu) * rstd * s1.x + b1.x;
    o1.y = (b.y - mu) * rstd * s1.y + b1.y;
    o1.z = (b.z - mu) * rstd * s1.z + b1.z;
    o1.w = (b.w - mu) * rstd * s1.w + b1.w;
    float4* yp = (float4*)(y + (size_t)row * DMODEL + lane * 8);
    yp[0] = o0;
    yp[1] = o1;
}

// ---------------- tf32 tensor-core GEMM ----------------
// C = [res +] act(A@B [+ bias]); A: MxK rm, B: KxN rm.
// Block tile 64x64, BK=32, 256 threads = 8 warps (4m x 2n), warp tile 16x32.
#define BM 64
#define BN 64
#define BKT 32
#define A_LD 36
#define B_LD 72

__device__ __forceinline__ uint32_t f2tf(float f) {
    uint32_t u;
    asm("cvt.rna.tf32.f32 %0, %1;" : "=r"(u) : "f"(f));
    return u;
}

__device__ __forceinline__ void mma8(float* c, const uint32_t* a, const uint32_t* b) {
    asm volatile(
        "mma.sync.aligned.m16n8k8.row.col.f32.tf32.tf32.f32 "
        "{%0,%1,%2,%3},{%4,%5,%6,%7},{%8,%9},{%0,%1,%2,%3};"
        : "+f"(c[0]), "+f"(c[1]), "+f"(c[2]), "+f"(c[3])
        : "r"(a[0]), "r"(a[1]), "r"(a[2]), "r"(a[3]), "r"(b[0]), "r"(b[1]));
}

__global__ __launch_bounds__(256) void gemm_tc(const float* __restrict__ A,
                                               const float* __restrict__ B,
                                               const float* __restrict__ bias,
                                               const float* __restrict__ res,
                                               float* __restrict__ C,
                                               int M, int N, int K, int flags) {
    __shared__ uint32_t As[2][BM * A_LD];
    __shared__ uint32_t Bs[2][BKT * B_LD];
    int tid = threadIdx.x;
    int lane = tid & 31, wid = tid >> 5;
    int wm = wid & 3, wn = wid >> 2;       // 4 x 2 warp grid
    int grp = lane >> 2, qk = lane & 3;
    int bm = blockIdx.y * BM, bn = blockIdx.x * BN;
    // float4 on B requires both in-bounds AND 16B-aligned rows (N % 4 == 0).
    bool bvec = ((N & 3) == 0) && (bn + BN <= N);

    float c[4][4];
    #pragma unroll
    for (int i = 0; i < 4; i++)
        #pragma unroll
        for (int j = 0; j < 4; j++) c[i][j] = 0.f;

    float4 ra[2], rb[2];

    // ---- prologue: load k0=0 ----
    {
        #pragma unroll
        for (int i = 0; i < 2; i++) {
            int idx = tid + 256 * i;
            int m = idx >> 3, kq = idx & 7;
            ra[i] = *(const float4*)(A + (size_t)(bm + m) * K + kq * 4);
        }
        #pragma unroll
        for (int i = 0; i < 2; i++) {
            int idx = tid + 256 * i;
            int k = idx >> 4, nq = idx & 15;
            if (bvec) {
                rb[i] = *(const float4*)(B + (size_t)k * N + bn + nq * 4);
            } else {
                int n = bn + nq * 4;
                rb[i].x = (n + 0 < N) ? B[(size_t)k * N + n + 0] : 0.f;
                rb[i].y = (n + 1 < N) ? B[(size_t)k * N + n + 1] : 0.f;
                rb[i].z = (n + 2 < N) ? B[(size_t)k * N + n + 2] : 0.f;
                rb[i].w = (n + 3 < N) ? B[(size_t)k * N + n + 3] : 0.f;
            }
        }
        #pragma unroll
        for (int i = 0; i < 2; i++) {
            int idx = tid + 256 * i;
            int m = idx >> 3, kq = idx & 7;
            uint32_t* p = &As[0][m * A_LD + kq * 4];
            p[0] = f2tf(ra[i].x); p[1] = f2tf(ra[i].y);
            p[2] = f2tf(ra[i].z); p[3] = f2tf(ra[i].w);
        }
        #pragma unroll
        for (int i = 0; i < 2; i++) {
            int idx = tid + 256 * i;
            int k = idx >> 4, nq = idx & 15;
            uint32_t* p = &Bs[0][k * B_LD + nq * 4];
            p[0] = f2tf(rb[i].x); p[1] = f2tf(rb[i].y);
            p[2] = f2tf(rb[i].z); p[3] = f2tf(rb[i].w);
        }
    }
    __syncthreads();

    int nk = K / BKT;
    for (int it = 0; it < nk; it++) {
        int buf = it & 1;
        bool has_next = (it + 1 < nk);
        if (has_next) {
            int k0 = (it + 1) * BKT;
            #pragma unroll
            for (int i = 0; i < 2; i++) {
                int idx = tid + 256 * i;
                int m = idx >> 3, kq = idx & 7;
                ra[i] = *(const float4*)(A + (size_t)(bm + m) * K + k0 + kq * 4);
            }
            #pragma unroll
            for (int i = 0; i < 2; i++) {
                int idx = tid + 256 * i;
                int k = idx >> 4, nq = idx & 15;
                if (bvec) {
                    rb[i] = *(const float4*)(B + (size_t)(k0 + k) * N + bn + nq * 4);
                } else {
                    int n = bn + nq * 4;
                    rb[i].x = (n + 0 < N) ? B[(size_t)(k0 + k) * N + n + 0] : 0.f;
                    rb[i].y = (n + 1 < N) ? B[(size_t)(k0 + k) * N + n + 1] : 0.f;
                    rb[i].z = (n + 2 < N) ? B[(size_t)(k0 + k) * N + n + 2] : 0.f;
                    rb[i].w = (n + 3 < N) ? B[(size_t)(k0 + k) * N + n + 3] : 0.f;
                }
            }
        }
        // compute on buf
        #pragma unroll
        for (int kk = 0; kk < BKT; kk += 8) {
            uint32_t a[4];
            int m0 = wm * 16 + grp;
            a[0] = As[buf][(m0) * A_LD + kk + qk];
            a[1] = As[buf][(m0 + 8) * A_LD + kk + qk];
            a[2] = As[buf][(m0) * A_LD + kk + qk + 4];
            a[3] = As[buf][(m0 + 8) * A_LD + kk + qk + 4];
            #pragma unroll
            for (int sj = 0; sj < 4; sj++) {
                uint32_t b[2];
                int n0 = wn * 32 + sj * 8 + grp;
                b[0] = Bs[buf][(kk + qk) * B_LD + n0];
                b[1] = Bs[buf][(kk + qk + 4) * B_LD + n0];
                mma8(c[sj], a, b);
            }
        }
        if (has_next) {
            int nb = (it + 1) & 1;
            #pragma unroll
            for (int i = 0; i < 2; i++) {
                int idx = tid + 256 * i;
                int m = idx >> 3, kq = idx & 7;
                uint32_t* p = &As[nb][m * A_LD + kq * 4];
                p[0] = f2tf(ra[i].x); p[1] = f2tf(ra[i].y);
                p[2] = f2tf(ra[i].z); p[3] = f2tf(ra[i].w);
            }
            #pragma unroll
            for (int i = 0; i < 2; i++) {
                int idx = tid + 256 * i;
                int k = idx >> 4, nq = idx & 15;
                uint32_t* p = &Bs[nb][k * B_LD + nq * 4];
                p[0] = f2tf(rb[i].x); p[1] = f2tf(rb[i].y);
                p[2] = f2tf(rb[i].z); p[3] = f2tf(rb[i].w);
            }
            __syncthreads();
        }
    }

    // ---- epilogue ----
    bool do_relu = (flags & 1);
    int r0 = bm + wm * 16 + grp;
    int r1 = r0 + 8;
    #pragma unroll
    for (int sj = 0; sj < 4; sj++) {
        int n = bn + wn * 32 + sj * 8 + qk * 2;
        #pragma unroll
        for (int jj = 0; jj < 2; jj++) {
            int nn = n + jj;
            if (nn < N) {
                float bv = bias ? bias[nn] : 0.f;
                float t0 = c[sj][0 + jj] + bv;
                float t1 = c[sj][2 + jj] + bv;
                if (do_relu) { t0 = fmaxf(t0, 0.f); t1 = fmaxf(t1, 0.f); }
                if (res) {
                    t0 += res[(size_t)r0 * N + nn];
                    t1 += res[(size_t)r1 * N + nn];
                }
                C[(size_t)r0 * N + nn] = t0;
                C[(size_t)r1 * N + nn] = t1;
            }
        }
    }
}

// ---------------- causal attention, split-K partials ----------------
// grid = (BATCH*NHEAD, NSPLIT), 512 threads; thread pair (q*2, q*2+1)
// handles one query row, each owning half of DK (16 dims).
__global__ __launch_bounds__(512) void attn_part(const float* __restrict__ qkv) {
    int bh = blockIdx.x;
    int s = blockIdx.y;
    int b = bh >> 3;
    int h = bh & 7;
    int tid = threadIdx.x;
    int q = tid >> 1;         // 0..255
    int half = tid & 1;       // 0/1 -> dims [half*16, half*16+16)
    int node0 = b * SEQ;
    int kbase = s * SPLITK;

    __shared__ float Ks[SPLITK * DK];
    __shared__ float Vs[SPLITK * DK];

    // stage K/V slice: 64 rows x 32 floats = 512 float4 each, 1 per thread
    {
        int row = tid >> 3, fq = tid & 7;
        const float* kp = qkv + (size_t)(node0 + kbase + row) * (3 * DMODEL) + DMODEL + h * DK;
        ((float4*)Ks)[tid] = ((const float4*)kp)[fq];
        ((float4*)Vs)[tid] = ((const float4*)(kp + DMODEL))[fq];
    }

    const float scale = 0.1767766952966369f;  // 1/sqrt(32)
    float4 qv[4];
    {
        const float* qp = qkv + (size_t)(node0 + q) * (3 * DMODEL) + h * DK + half * 16;
        #pragma unroll
        for (int i = 0; i < 4; i++) {
            qv[i] = ((const float4*)qp)[i];
            qv[i].x *= scale; qv[i].y *= scale; qv[i].z *= scale; qv[i].w *= scale;
        }
    }
    __syncthreads();

    int node = node0 + q;
    int pidx = (s * NNODES + node) * NHEAD + h;

    float m = -1e30f, l = 0.f;
    float4 acc[4];
    #pragma unroll
    for (int i = 0; i < 4; i++) acc[i] = make_float4(0.f, 0.f, 0.f, 0.f);

    // kbase is a multiple of 64; warp covers 16 consecutive q -> guard is warp-uniform
    if (q >= kbase) {
        int lim = q - kbase;                       // mask: local j <= lim
        if (lim > SPLITK - 1) lim = SPLITK - 1;
        int jmaxw = (q - kbase) | 15;              // warp-uniform (16 q per warp)
        if (jmaxw > SPLITK - 1) jmaxw = SPLITK - 1;
        for (int j = 0; j <= jmaxw; j++) {
            const float4* kr = (const float4*)(Ks + j * DK + half * 16);
            float sc = 0.f;
            #pragma unroll
            for (int i = 0; i < 4; i++) {
                float4 kvv = kr[i];
                sc = fmaf(qv[i].x, kvv.x, sc);
                sc = fmaf(qv[i].y, kvv.y, sc);
                sc = fmaf(qv[i].z, kvv.z, sc);
                sc = fmaf(qv[i].w, kvv.w, sc);
            }
            sc += __shfl_xor_sync(0xffffffffu, sc, 1);  // combine the two halves
            if (j > lim) sc = -1e30f;
            float mn = fmaxf(m, sc);
            float corr = __expf(m - mn);
            float p = __expf(sc - mn);
            l = l * corr + p;
            const float4* vr = (const float4*)(Vs + j * DK + half * 16);
            #pragma unroll
            for (int i = 0; i < 4; i++) {
                float4 vv = vr[i];
                acc[i].x = acc[i].x * corr + p * vv.x;
                acc[i].y = acc[i].y * corr + p * vv.y;
                acc[i].z = acc[i].z * corr + p * vv.z;
                acc[i].w = acc[i].w * corr + p * vv.w;
            }
            m = mn;
        }
        float* ap = g_pacc + (size_t)pidx * DK + half * 16;
        #pragma unroll
        for (int i = 0; i < 4; i++) ((float4*)ap)[i] = acc[i];
    }
    if (half == 0) {
        g_pm[pidx] = m;
        g_pl[pidx] = l;
    }
}

// combine: grid NNODES, 256 threads = 8 heads x 32 dims
__global__ void attn_combine(float* __restrict__ z) {
    int node = blockIdx.x;
    int h = threadIdx.x >> 5;
    int d = threadIdx.x & 31;

    float ms[NSPLIT], ls[NSPLIT];
    float M = -1e30f;
    #pragma unroll
    for (int s = 0; s < NSPLIT; s++) {
        int pidx = (s * NNODES + node) * NHEAD + h;
        ms[s] = g_pm[pidx];
        ls[s] = g_pl[pidx];
        M = fmaxf(M, ms[s]);
    }
    float wsum = 0.f, zz = 0.f;
    #pragma unroll
    for (int s = 0; s < NSPLIT; s++) {
        float w = __expf(ms[s] - M);
        wsum += ls[s] * w;
        int pidx = (s * NNODES + node) * NHEAD + h;
        zz += w * g_pacc[(size_t)pidx * DK + d];
    }
    z[(size_t)node * DMODEL + h * DK + d] = zz / wsum;
}

// ---------------- log-softmax over VOCAB=259 ----------------
__global__ void lsm_kernel(const float* __restrict__ logits, float* __restrict__ out) {
    int row = blockIdx.x;
    int tid = threadIdx.x;  // 256
    const float* lp = logits + (size_t)row * VOCAB;
    float v0 = lp[tid];
    float v1 = (tid < VOCAB - 256) ? lp[256 + tid] : -1e30f;
    float mx = fmaxf(v0, v1);
    #pragma unroll
    for (int o = 16; o > 0; o >>= 1)
        mx = fmaxf(mx, __shfl_down_sync(0xffffffffu, mx, o));
    __shared__ float shm[8];
    int w = tid >> 5, l = tid & 31;
    if (l == 0) shm[w] = mx;
    __syncthreads();
    __shared__ float M_s, lse_s;
    if (tid == 0) {
        float m = shm[0];
        #pragma unroll
        for (int i = 1; i < 8; i++) m = fmaxf(m, shm[i]);
        M_s = m;
    }
    __syncthreads();
    float M = M_s;
    float e = expf(v0 - M) + ((tid < VOCAB - 256) ? expf(v1 - M) : 0.f);
    #pragma unroll
    for (int o = 16; o > 0; o >>= 1)
        e += __shfl_down_sync(0xffffffffu, e, o);
    if (l == 0) shm[w] = e;
    __syncthreads();
    if (tid == 0) {
        float s = 0.f;
        #pragma unroll
        for (int i = 0; i < 8; i++) s += shm[i];
        lse_s = logf(s) + M;
    }
    __syncthreads();
    float lse = lse_s;
    float* op = out + (size_t)row * VOCAB;
    op[tid] = v0 - lse;
    if (tid < VOCAB - 256) op[256 + tid] = v1 - lse;
}

// ---------------- launch ----------------
extern "C" void kernel_launch(void* const* d_in, const int* in_sizes, int n_in,
                              void* d_out, int out_size) {
    const int*   tokens    = (const int*)d_in[0];
    const int*   positions = (const int*)d_in[1];
    // d_in[2], d_in[3]: edge_src/edge_dst — exact tril structure, handled analytically
    const float* coord_emb = (const float*)d_in[4];
    const float* pos_emb   = (const float*)d_in[5];
    const float* value_emb = (const float*)d_in[6];
    const float* ln1_scale = (const float*)d_in[7];
    const float* ln1_bias  = (const float*)d_in[8];
    const float* Wqkv      = (const float*)d_in[9];
    const float* Wo        = (const float*)d_in[10];
    const float* ln2_scale = (const float*)d_in[11];
    const float* ln2_bias  = (const float*)d_in[12];
    const float* W1        = (const float*)d_in[13];
    const float* b1        = (const float*)d_in[14];
    const float* W2        = (const float*)d_in[15];
    const float* b2        = (const float*)d_in[16];
    const float* lnf_scale = (const float*)d_in[17];
    const float* lnf_bias  = (const float*)d_in[18];
    const float* Wg        = (const float*)d_in[19];
    const float* bg        = (const float*)d_in[20];
    float* out = (float*)d_out;

    float *x, *xn, *qkv, *z, *h, *logits;
    cudaGetSymbolAddress((void**)&x, g_x);
    cudaGetSymbolAddress((void**)&xn, g_xn);
    cudaGetSymbolAddress((void**)&qkv, g_qkv);
    cudaGetSymbolAddress((void**)&z, g_z);
    cudaGetSymbolAddress((void**)&h, g_h);
    cudaGetSymbolAddress((void**)&logits, g_logits);

    embed_kernel<<<NNODES, DMODEL>>>(tokens, positions, coord_emb, pos_emb, value_emb, x);

    for (int i = 0; i < NLAYERS; i++) {
        const float* wqkv_i = Wqkv + (size_t)i * DMODEL * 3 * DMODEL;
        const float* wo_i   = Wo   + (size_t)i * DMODEL * DMODEL;
        const float* w1_i   = W1   + (size_t)i * DMODEL * DFF;
        const float* w2_i   = W2   + (size_t)i * DFF * DMODEL;

        // attention block
        ln_kernel<<<NNODES / 8, 256>>>(x, ln1_scale + i * DMODEL, ln1_bias + i * DMODEL, xn);
        {
            dim3 grid((3 * DMODEL) / BN, NNODES / BM);
            gemm_tc<<<grid, 256>>>(xn, wqkv_i, nullptr, nullptr, qkv,
                                   NNODES, 3 * DMODEL, DMODEL, 0);
        }
        attn_part<<<dim3(BATCH * NHEAD, NSPLIT), 512>>>(qkv);
        attn_combine<<<NNODES, 256>>>(z);
        {
            dim3 grid(DMODEL / BN, NNODES / BM);
            gemm_tc<<<grid, 256>>>(z, wo_i, nullptr, x, x,
                                   NNODES, DMODEL, DMODEL, 0);
        }
        // FFN block
        ln_kernel<<<NNODES / 8, 256>>>(x, ln2_scale + i * DMODEL, ln2_bias + i * DMODEL, xn);
        {
            dim3 grid(DFF / BN, NNODES / BM);
            gemm_tc<<<grid, 256>>>(xn, w1_i, b1 + i * DFF, nullptr, h,
                                   NNODES, DFF, DMODEL, 1 /*relu*/);
        }
        {
            dim3 grid(DMODEL / BN, NNODES / BM);
            gemm_tc<<<grid, 256>>>(h, w2_i, b2 + i * DMODEL, x, x,
                                   NNODES, DMODEL, DFF, 0);
        }
    }

    ln_kernel<<<NNODES / 8, 256>>>(x, lnf_scale, lnf_bias, xn);
    {
        dim3 grid((VOCAB + BN - 1) / BN, NNODES / BM);
        gemm_tc<<<grid, 256>>>(xn, Wg, bg, nullptr, logits,
                               NNODES, VOCAB, DMODEL, 0);
    }
    lsm_kernel<<<NNODES, 256>>>(logits, out);
}